// round 1
// baseline (speedup 1.0000x reference)
#include <cuda_runtime.h>
#include <math.h>

#define CH 192
#define DD 24
#define BB 8
#define LL 4096
#define NTOK (BB*LL)
#define BK 128
#define SUB 16

// Scratch for Q, K, V projections: [NTOK][24] each (~3 MB each)
__device__ float g_q[NTOK*DD];
__device__ float g_k[NTOK*DD];
__device__ float g_v[NTOK*DD];

// ---------------------------------------------------------------------------
// Kernel 1: fused QKV projection. One thread per token, 72 accumulators.
// Weights live in dynamic smem as Ws[c][72] (q|k|v concatenated), read as
// float4 broadcasts.
// ---------------------------------------------------------------------------
__global__ __launch_bounds__(128) void proj_kernel(
    const float* __restrict__ x, const float* __restrict__ wq,
    const float* __restrict__ wk, const float* __restrict__ wv)
{
    extern __shared__ float Ws[];  // [192][72] = 55296 B
    int tid = threadIdx.x;
    for (int i = tid; i < CH*DD; i += 128) {
        int c = i / DD, d = i - c*DD;
        Ws[c*72 + d]      = wq[i];
        Ws[c*72 + 24 + d] = wk[i];
        Ws[c*72 + 48 + d] = wv[i];
    }
    __syncthreads();

    int tok = blockIdx.x * 128 + tid;
    float acc[72];
    #pragma unroll
    for (int o = 0; o < 72; o++) acc[o] = 0.f;

    const float4* xr = reinterpret_cast<const float4*>(x + (size_t)tok * CH);
    #pragma unroll 1
    for (int c4 = 0; c4 < CH/4; c4++) {
        float4 xv = xr[c4];
        float xs[4] = {xv.x, xv.y, xv.z, xv.w};
        #pragma unroll
        for (int j = 0; j < 4; j++) {
            const float4* wrow = reinterpret_cast<const float4*>(Ws + (c4*4 + j)*72);
            #pragma unroll
            for (int o4 = 0; o4 < 18; o4++) {
                float4 w = wrow[o4];
                acc[o4*4+0] = fmaf(xs[j], w.x, acc[o4*4+0]);
                acc[o4*4+1] = fmaf(xs[j], w.y, acc[o4*4+1]);
                acc[o4*4+2] = fmaf(xs[j], w.z, acc[o4*4+2]);
                acc[o4*4+3] = fmaf(xs[j], w.w, acc[o4*4+3]);
            }
        }
    }

    float4* qo = reinterpret_cast<float4*>(g_q + (size_t)tok * DD);
    float4* ko = reinterpret_cast<float4*>(g_k + (size_t)tok * DD);
    float4* vo = reinterpret_cast<float4*>(g_v + (size_t)tok * DD);
    #pragma unroll
    for (int i = 0; i < 6; i++) {
        qo[i] = make_float4(acc[i*4+0],    acc[i*4+1],    acc[i*4+2],    acc[i*4+3]);
        ko[i] = make_float4(acc[24+i*4+0], acc[24+i*4+1], acc[24+i*4+2], acc[24+i*4+3]);
        vo[i] = make_float4(acc[48+i*4+0], acc[48+i*4+1], acc[48+i*4+2], acc[48+i*4+3]);
    }
}

// ---------------------------------------------------------------------------
// Kernel 2: flash attention + fused (attn @ Wo)*gamma + residual epilogue.
// 1 query per thread, 128 threads/block, grid (32 qtiles, 8 batches).
// ---------------------------------------------------------------------------
__global__ __launch_bounds__(128) void attn_kernel(
    const float* __restrict__ tensor, const float* __restrict__ wo,
    const float* __restrict__ gammap, float* __restrict__ out)
{
    __shared__ float smem[2*BK*DD];   // 24 KB: K tile | V tile; reused for Wo
    float* Ksm = smem;
    float* Vsm = smem + BK*DD;

    int tid = threadIdx.x;
    int qt = blockIdx.x, b = blockIdx.y;
    int tok = b*LL + qt*128 + tid;

    float q[24];
    {
        const float4* qr = reinterpret_cast<const float4*>(g_q + (size_t)tok * DD);
        #pragma unroll
        for (int i = 0; i < 6; i++) {
            float4 t = qr[i];
            q[i*4+0] = t.x; q[i*4+1] = t.y; q[i*4+2] = t.z; q[i*4+3] = t.w;
        }
    }

    float m = -INFINITY, l = 0.f;
    float acc[24];
    #pragma unroll
    for (int d = 0; d < 24; d++) acc[d] = 0.f;

    const float4* Kg = reinterpret_cast<const float4*>(g_k + (size_t)b * LL * DD);
    const float4* Vg = reinterpret_cast<const float4*>(g_v + (size_t)b * LL * DD);

    #pragma unroll 1
    for (int kt = 0; kt < LL/BK; kt++) {
        __syncthreads();
        {
            float4* kd = reinterpret_cast<float4*>(Ksm);
            float4* vd = reinterpret_cast<float4*>(Vsm);
            const float4* ks = Kg + kt * BK * 6;
            const float4* vs = Vg + kt * BK * 6;
            #pragma unroll
            for (int i = 0; i < 6; i++) {
                kd[tid + i*128] = ks[tid + i*128];
                vd[tid + i*128] = vs[tid + i*128];
            }
        }
        __syncthreads();

        #pragma unroll 1
        for (int sub = 0; sub < BK/SUB; sub++) {
            float s[SUB];
            #pragma unroll
            for (int jj = 0; jj < SUB; jj++) {
                const float4* kr = reinterpret_cast<const float4*>(Ksm + (sub*SUB + jj)*DD);
                float4 k0 = kr[0], k1 = kr[1], k2 = kr[2], k3 = kr[3], k4 = kr[4], k5 = kr[5];
                float a0 = 0.f, a1 = 0.f, a2 = 0.f, a3 = 0.f;
                a0 = fmaf(q[0],  k0.x, a0); a1 = fmaf(q[1],  k0.y, a1);
                a2 = fmaf(q[2],  k0.z, a2); a3 = fmaf(q[3],  k0.w, a3);
                a0 = fmaf(q[4],  k1.x, a0); a1 = fmaf(q[5],  k1.y, a1);
                a2 = fmaf(q[6],  k1.z, a2); a3 = fmaf(q[7],  k1.w, a3);
                a0 = fmaf(q[8],  k2.x, a0); a1 = fmaf(q[9],  k2.y, a1);
                a2 = fmaf(q[10], k2.z, a2); a3 = fmaf(q[11], k2.w, a3);
                a0 = fmaf(q[12], k3.x, a0); a1 = fmaf(q[13], k3.y, a1);
                a2 = fmaf(q[14], k3.z, a2); a3 = fmaf(q[15], k3.w, a3);
                a0 = fmaf(q[16], k4.x, a0); a1 = fmaf(q[17], k4.y, a1);
                a2 = fmaf(q[18], k4.z, a2); a3 = fmaf(q[19], k4.w, a3);
                a0 = fmaf(q[20], k5.x, a0); a1 = fmaf(q[21], k5.y, a1);
                a2 = fmaf(q[22], k5.z, a2); a3 = fmaf(q[23], k5.w, a3);
                s[jj] = (a0 + a1) + (a2 + a3);
            }

            float tmax = s[0];
            #pragma unroll
            for (int jj = 1; jj < SUB; jj++) tmax = fmaxf(tmax, s[jj]);
            float mn = fmaxf(m, tmax);
            float scale = __expf(m - mn);   // exp(-inf)=0 handles first tile
            m = mn;
            l *= scale;
            #pragma unroll
            for (int d = 0; d < 24; d++) acc[d] *= scale;

            #pragma unroll
            for (int jj = 0; jj < SUB; jj++) {
                float p = __expf(s[jj] - m);
                l += p;
                const float4* vr = reinterpret_cast<const float4*>(Vsm + (sub*SUB + jj)*DD);
                float4 v0 = vr[0], v1 = vr[1], v2 = vr[2], v3 = vr[3], v4 = vr[4], v5 = vr[5];
                acc[0]  = fmaf(p, v0.x, acc[0]);  acc[1]  = fmaf(p, v0.y, acc[1]);
                acc[2]  = fmaf(p, v0.z, acc[2]);  acc[3]  = fmaf(p, v0.w, acc[3]);
                acc[4]  = fmaf(p, v1.x, acc[4]);  acc[5]  = fmaf(p, v1.y, acc[5]);
                acc[6]  = fmaf(p, v1.z, acc[6]);  acc[7]  = fmaf(p, v1.w, acc[7]);
                acc[8]  = fmaf(p, v2.x, acc[8]);  acc[9]  = fmaf(p, v2.y, acc[9]);
                acc[10] = fmaf(p, v2.z, acc[10]); acc[11] = fmaf(p, v2.w, acc[11]);
                acc[12] = fmaf(p, v3.x, acc[12]); acc[13] = fmaf(p, v3.y, acc[13]);
                acc[14] = fmaf(p, v3.z, acc[14]); acc[15] = fmaf(p, v3.w, acc[15]);
                acc[16] = fmaf(p, v4.x, acc[16]); acc[17] = fmaf(p, v4.y, acc[17]);
                acc[18] = fmaf(p, v4.z, acc[18]); acc[19] = fmaf(p, v4.w, acc[19]);
                acc[20] = fmaf(p, v5.x, acc[20]); acc[21] = fmaf(p, v5.y, acc[21]);
                acc[22] = fmaf(p, v5.z, acc[22]); acc[23] = fmaf(p, v5.w, acc[23]);
            }
        }
    }

    // ---- Epilogue: out = tensor + gamma * (attn @ Wo), Wo in reused smem ----
    __syncthreads();
    {
        float4* wd = reinterpret_cast<float4*>(smem);
        const float4* wsrc = reinterpret_cast<const float4*>(wo);
        #pragma unroll
        for (int i = 0; i < 9; i++) wd[tid + i*128] = wsrc[tid + i*128];
    }
    __syncthreads();

    float inv = 1.0f / l;
    float attn[24];
    #pragma unroll
    for (int d = 0; d < 24; d++) attn[d] = acc[d] * inv;

    float g = *gammap;
    const float4* tr = reinterpret_cast<const float4*>(tensor + (size_t)tok * CH);
    float4* orow = reinterpret_cast<float4*>(out + (size_t)tok * CH);
    const float4* wos = reinterpret_cast<const float4*>(smem);

    #pragma unroll 1
    for (int c4 = 0; c4 < CH/4; c4++) {
        float4 t = tr[c4];
        float sx = 0.f, sy = 0.f, sz = 0.f, sw = 0.f;
        #pragma unroll
        for (int d = 0; d < 24; d++) {
            float4 w = wos[d*48 + c4];
            sx = fmaf(attn[d], w.x, sx);
            sy = fmaf(attn[d], w.y, sy);
            sz = fmaf(attn[d], w.z, sz);
            sw = fmaf(attn[d], w.w, sw);
        }
        t.x = fmaf(g, sx, t.x);
        t.y = fmaf(g, sy, t.y);
        t.z = fmaf(g, sz, t.z);
        t.w = fmaf(g, sw, t.w);
        orow[c4] = t;
    }
}

extern "C" void kernel_launch(void* const* d_in, const int* in_sizes, int n_in,
                              void* d_out, int out_size)
{
    const float* tensor = (const float*)d_in[0];
    const float* wq     = (const float*)d_in[1];
    const float* wk     = (const float*)d_in[2];
    const float* wv     = (const float*)d_in[3];
    const float* wo     = (const float*)d_in[4];
    const float* gamma  = (const float*)d_in[5];
    float* out = (float*)d_out;

    // 55296 B dynamic smem > 48 KB static limit; attribute call is idempotent
    // and not a stream op (capture-safe).
    cudaFuncSetAttribute(proj_kernel, cudaFuncAttributeMaxDynamicSharedMemorySize, 72*CH*4);

    proj_kernel<<<NTOK/128, 128, 72*CH*4>>>(tensor, wq, wk, wv);

    dim3 g2(LL/BK, BB);
    attn_kernel<<<g2, 128>>>(tensor, wo, gamma, out);
}

// round 3
// speedup vs baseline: 2.9484x; 2.9484x over previous
#include <cuda_runtime.h>
#include <cuda_bf16.h>
#include <cstdint>
#include <math.h>

#define CH 192
#define DD 24
#define BB 8
#define LL 4096
#define NTOK (BB*LL)
#define BQ 128
#define BK 256
#define NKT (LL/BK)

#define QPAD 28
#define KPAD 28
#define APAD 26

// smem float offsets (attn kernel)
#define OFF_Q 0                      // 128*28 = 3584 floats
#define OFF_K 3584                   // 256*28 = 7168 floats
#define OFF_V (3584+7168)            // 128*24 = 3072 words (bf16x2 pairs)
#define SM_FLOATS (OFF_V + 3072)     // 13824 floats = 55296 B

__device__ float g_q[NTOK*DD];
__device__ float g_k[NTOK*DD];
__device__ float g_v[NTOK*DD];

// ---------------------------------------------------------------------------
// mma.sync helpers (sm_80+ PTX, valid on sm_100 base target)
// ---------------------------------------------------------------------------
__device__ __forceinline__ void mma_tf32(float* c, const uint32_t* a, uint32_t b0, uint32_t b1){
    asm volatile("mma.sync.aligned.m16n8k8.row.col.f32.tf32.tf32.f32 "
        "{%0,%1,%2,%3}, {%4,%5,%6,%7}, {%8,%9}, {%0,%1,%2,%3};"
        : "+f"(c[0]), "+f"(c[1]), "+f"(c[2]), "+f"(c[3])
        : "r"(a[0]), "r"(a[1]), "r"(a[2]), "r"(a[3]), "r"(b0), "r"(b1));
}
__device__ __forceinline__ void mma_bf16(float* c, const uint32_t* a, uint32_t b0, uint32_t b1){
    asm volatile("mma.sync.aligned.m16n8k16.row.col.f32.bf16.bf16.f32 "
        "{%0,%1,%2,%3}, {%4,%5,%6,%7}, {%8,%9}, {%0,%1,%2,%3};"
        : "+f"(c[0]), "+f"(c[1]), "+f"(c[2]), "+f"(c[3])
        : "r"(a[0]), "r"(a[1]), "r"(a[2]), "r"(a[3]), "r"(b0), "r"(b1));
}
__device__ __forceinline__ uint32_t packbf(float hi, float lo){
    uint32_t r;
    asm("cvt.rn.bf16x2.f32 %0, %1, %2;" : "=r"(r) : "f"(hi), "f"(lo));
    return r;
}

// ---------------------------------------------------------------------------
// Kernel 1: fused QKV projection (unchanged from R1)
// ---------------------------------------------------------------------------
__global__ __launch_bounds__(128) void proj_kernel(
    const float* __restrict__ x, const float* __restrict__ wq,
    const float* __restrict__ wk, const float* __restrict__ wv)
{
    extern __shared__ float Ws[];
    int tid = threadIdx.x;
    for (int i = tid; i < CH*DD; i += 128) {
        int c = i / DD, d = i - c*DD;
        Ws[c*72 + d]      = wq[i];
        Ws[c*72 + 24 + d] = wk[i];
        Ws[c*72 + 48 + d] = wv[i];
    }
    __syncthreads();

    int tok = blockIdx.x * 128 + tid;
    float acc[72];
    #pragma unroll
    for (int o = 0; o < 72; o++) acc[o] = 0.f;

    const float4* xr = reinterpret_cast<const float4*>(x + (size_t)tok * CH);
    #pragma unroll 1
    for (int c4 = 0; c4 < CH/4; c4++) {
        float4 xv = xr[c4];
        float xs[4] = {xv.x, xv.y, xv.z, xv.w};
        #pragma unroll
        for (int j = 0; j < 4; j++) {
            const float4* wrow = reinterpret_cast<const float4*>(Ws + (c4*4 + j)*72);
            #pragma unroll
            for (int o4 = 0; o4 < 18; o4++) {
                float4 w = wrow[o4];
                acc[o4*4+0] = fmaf(xs[j], w.x, acc[o4*4+0]);
                acc[o4*4+1] = fmaf(xs[j], w.y, acc[o4*4+1]);
                acc[o4*4+2] = fmaf(xs[j], w.z, acc[o4*4+2]);
                acc[o4*4+3] = fmaf(xs[j], w.w, acc[o4*4+3]);
            }
        }
    }

    float4* qo = reinterpret_cast<float4*>(g_q + (size_t)tok * DD);
    float4* ko = reinterpret_cast<float4*>(g_k + (size_t)tok * DD);
    float4* vo = reinterpret_cast<float4*>(g_v + (size_t)tok * DD);
    #pragma unroll
    for (int i = 0; i < 6; i++) {
        qo[i] = make_float4(acc[i*4+0],    acc[i*4+1],    acc[i*4+2],    acc[i*4+3]);
        ko[i] = make_float4(acc[24+i*4+0], acc[24+i*4+1], acc[24+i*4+2], acc[24+i*4+3]);
        vo[i] = make_float4(acc[48+i*4+0], acc[48+i*4+1], acc[48+i*4+2], acc[48+i*4+3]);
    }
}

// ---------------------------------------------------------------------------
// Kernel 2: mma.sync flash attention (tf32 QK^T, bf16 PV) + fused epilogue.
// 128 threads / 4 warps; warp owns 32 queries (2 M-tiles of m16n8k8/k16).
// ---------------------------------------------------------------------------
__global__ __launch_bounds__(128) void attn_mma_kernel(
    const float* __restrict__ tensor, const float* __restrict__ wo,
    const float* __restrict__ gammap, float* __restrict__ out)
{
    extern __shared__ float sm[];
    float* Qs = sm + OFF_Q;
    float* Ks = sm + OFF_K;
    uint32_t* Vb = reinterpret_cast<uint32_t*>(sm + OFF_V);

    const int tid  = threadIdx.x;
    const int w    = tid >> 5;
    const int lane = tid & 31;
    const int g    = lane >> 2;   // row group 0..7
    const int tig  = lane & 3;    // thread-in-group 0..3
    const int qt = blockIdx.x, b = blockIdx.y;

    // ---- stage Q tile: row = tid, pad 28 ----
    {
        const float4* src = reinterpret_cast<const float4*>(g_q + (size_t)(b*LL + qt*BQ + tid)*DD);
        float4* dst = reinterpret_cast<float4*>(Qs + tid*QPAD);
        #pragma unroll
        for (int i = 0; i < 6; i++) dst[i] = src[i];
    }
    __syncthreads();

    // ---- Q fragments (A of m16n8k8), resident all kernel: qa[mt][ks][4] ----
    uint32_t qa[2][3][4];
    {
        int qb = w*32;
        #pragma unroll
        for (int mt = 0; mt < 2; mt++)
            #pragma unroll
            for (int ks = 0; ks < 3; ks++) {
                const float* r0 = Qs + (qb + mt*16 + g)*QPAD + ks*8 + tig;
                const float* r1 = r0 + 8*QPAD;
                qa[mt][ks][0] = __float_as_uint(r0[0]);
                qa[mt][ks][1] = __float_as_uint(r1[0]);
                qa[mt][ks][2] = __float_as_uint(r0[4]);
                qa[mt][ks][3] = __float_as_uint(r1[4]);
            }
    }

    float m[4], l[4];
    #pragma unroll
    for (int i = 0; i < 4; i++) { m[i] = -INFINITY; l[i] = 0.f; }
    float o[2][3][4];
    #pragma unroll
    for (int mt = 0; mt < 2; mt++)
        #pragma unroll
        for (int dn = 0; dn < 3; dn++)
            #pragma unroll
            for (int j = 0; j < 4; j++) o[mt][dn][j] = 0.f;

    // ================= main loop over key tiles =================
    #pragma unroll 1
    for (int kt = 0; kt < NKT; kt++) {
        __syncthreads();
        // stage K: 256 rows, pad 28
        {
            #pragma unroll
            for (int rr = 0; rr < 2; rr++) {
                int r = tid + rr*128;
                const float4* src = reinterpret_cast<const float4*>(g_k + (size_t)(b*LL + kt*BK + r)*DD);
                float4* dst = reinterpret_cast<float4*>(Ks + r*KPAD);
                #pragma unroll
                for (int i = 0; i < 6; i++) dst[i] = src[i];
            }
        }
        // stage V as bf16x2 key-pair words: Vb[kp*24 + d] = {lo=V[2kp][d], hi=V[2kp+1][d]}
        {
            const float* vsrc = g_v + (size_t)(b*LL + kt*BK)*DD;
            #pragma unroll
            for (int i = 0; i < 24; i++) {
                int idx = tid + i*128;           // < 3072
                int kp = idx / 24, d = idx - kp*24;
                float ve = vsrc[(2*kp)*DD + d];
                float vo_ = vsrc[(2*kp+1)*DD + d];
                Vb[idx] = packbf(vo_, ve);
            }
        }
        __syncthreads();

        // ---- 8 chunks of 32 keys ----
        #pragma unroll 1
        for (int ck = 0; ck < 8; ck++) {
            float s[2][4][4];
            #pragma unroll
            for (int nt = 0; nt < 4; nt++)
                #pragma unroll
                for (int j = 0; j < 4; j++) { s[0][nt][j] = 0.f; s[1][nt][j] = 0.f; }

            // S = Q K^T  (tf32)
            #pragma unroll
            for (int nt = 0; nt < 4; nt++) {
                const float* kr = Ks + (ck*32 + nt*8 + g)*KPAD + tig;
                #pragma unroll
                for (int ks = 0; ks < 3; ks++) {
                    uint32_t b0 = __float_as_uint(kr[ks*8]);
                    uint32_t b1 = __float_as_uint(kr[ks*8 + 4]);
                    mma_tf32(s[0][nt], qa[0][ks], b0, b1);
                    mma_tf32(s[1][nt], qa[1][ks], b0, b1);
                }
            }

            // online softmax (per row-half), then p in-place into s
            float sc[4];
            #pragma unroll
            for (int mt = 0; mt < 2; mt++)
                #pragma unroll
                for (int h = 0; h < 2; h++) {
                    int idx = mt*2 + h;
                    float mx = s[mt][0][h*2];
                    mx = fmaxf(mx, s[mt][0][h*2+1]);
                    #pragma unroll
                    for (int nt = 1; nt < 4; nt++) {
                        mx = fmaxf(mx, s[mt][nt][h*2]);
                        mx = fmaxf(mx, s[mt][nt][h*2+1]);
                    }
                    mx = fmaxf(mx, __shfl_xor_sync(0xffffffffu, mx, 1));
                    mx = fmaxf(mx, __shfl_xor_sync(0xffffffffu, mx, 2));
                    float mn = fmaxf(m[idx], mx);
                    float scale = __expf(m[idx] - mn);
                    m[idx] = mn;
                    float ls = 0.f;
                    #pragma unroll
                    for (int nt = 0; nt < 4; nt++) {
                        float p0 = __expf(s[mt][nt][h*2]   - mn);
                        float p1 = __expf(s[mt][nt][h*2+1] - mn);
                        s[mt][nt][h*2]   = p0;
                        s[mt][nt][h*2+1] = p1;
                        ls += p0 + p1;
                    }
                    ls += __shfl_xor_sync(0xffffffffu, ls, 1);
                    ls += __shfl_xor_sync(0xffffffffu, ls, 2);
                    l[idx] = l[idx]*scale + ls;
                    sc[idx] = scale;
                    #pragma unroll
                    for (int dn = 0; dn < 3; dn++) {
                        o[mt][dn][h*2]   *= scale;
                        o[mt][dn][h*2+1] *= scale;
                    }
                }
            (void)sc;

            // O += P V  (bf16), K-dim = 32 keys = 2 ksteps of 16
            #pragma unroll
            for (int ks2 = 0; ks2 < 2; ks2++) {
                uint32_t pa[2][4];
                #pragma unroll
                for (int mt = 0; mt < 2; mt++) {
                    pa[mt][0] = packbf(s[mt][ks2*2][1],   s[mt][ks2*2][0]);
                    pa[mt][1] = packbf(s[mt][ks2*2][3],   s[mt][ks2*2][2]);
                    pa[mt][2] = packbf(s[mt][ks2*2+1][1], s[mt][ks2*2+1][0]);
                    pa[mt][3] = packbf(s[mt][ks2*2+1][3], s[mt][ks2*2+1][2]);
                }
                const uint32_t* vr = Vb + (ck*16 + ks2*8 + tig)*24 + g;
                #pragma unroll
                for (int dn = 0; dn < 3; dn++) {
                    uint32_t b0 = vr[dn*8];
                    uint32_t b1 = vr[dn*8 + 4*24];
                    mma_bf16(o[0][dn], pa[0], b0, b1);
                    mma_bf16(o[1][dn], pa[1], b0, b1);
                }
            }
        }
    }

    // ---- write normalized attn to smem (transpose bounce), stage Wo ----
    __syncthreads();
    {
        #pragma unroll
        for (int mt = 0; mt < 2; mt++)
            #pragma unroll
            for (int h = 0; h < 2; h++) {
                float inv = 1.0f / l[mt*2 + h];
                int row = w*32 + mt*16 + g + h*8;
                #pragma unroll
                for (int dn = 0; dn < 3; dn++) {
                    sm[row*APAD + dn*8 + 2*tig]     = o[mt][dn][h*2]   * inv;
                    sm[row*APAD + dn*8 + 2*tig + 1] = o[mt][dn][h*2+1] * inv;
                }
            }
        float4* wd = reinterpret_cast<float4*>(Ks);
        const float4* ws = reinterpret_cast<const float4*>(wo);
        #pragma unroll
        for (int i = 0; i < 9; i++) wd[tid + i*128] = ws[tid + i*128];
    }
    __syncthreads();

    // ---- epilogue: out = tensor + gamma * attn @ Wo ----
    float attn[DD];
    #pragma unroll
    for (int d = 0; d < DD; d++) attn[d] = sm[tid*APAD + d];

    float gm = *gammap;
    int tok = b*LL + qt*BQ + tid;
    const float4* tr = reinterpret_cast<const float4*>(tensor + (size_t)tok * CH);
    float4* orow = reinterpret_cast<float4*>(out + (size_t)tok * CH);
    const float4* wos = reinterpret_cast<const float4*>(Ks);

    #pragma unroll 1
    for (int c4 = 0; c4 < CH/4; c4++) {
        float4 t = tr[c4];
        float sx = 0.f, sy = 0.f, sz = 0.f, sw = 0.f;
        #pragma unroll
        for (int d = 0; d < DD; d++) {
            float4 wv4 = wos[d*48 + c4];
            sx = fmaf(attn[d], wv4.x, sx);
            sy = fmaf(attn[d], wv4.y, sy);
            sz = fmaf(attn[d], wv4.z, sz);
            sw = fmaf(attn[d], wv4.w, sw);
        }
        t.x = fmaf(gm, sx, t.x);
        t.y = fmaf(gm, sy, t.y);
        t.z = fmaf(gm, sz, t.z);
        t.w = fmaf(gm, sw, t.w);
        orow[c4] = t;
    }
}

extern "C" void kernel_launch(void* const* d_in, const int* in_sizes, int n_in,
                              void* d_out, int out_size)
{
    const float* tensor = (const float*)d_in[0];
    const float* wq     = (const float*)d_in[1];
    const float* wk     = (const float*)d_in[2];
    const float* wv     = (const float*)d_in[3];
    const float* wo     = (const float*)d_in[4];
    const float* gamma  = (const float*)d_in[5];
    float* out = (float*)d_out;

    cudaFuncSetAttribute(proj_kernel, cudaFuncAttributeMaxDynamicSharedMemorySize, 72*CH*4);
    cudaFuncSetAttribute(attn_mma_kernel, cudaFuncAttributeMaxDynamicSharedMemorySize, SM_FLOATS*4);

    proj_kernel<<<NTOK/128, 128, 72*CH*4>>>(tensor, wq, wk, wv);

    dim3 g2(LL/BQ, BB);
    attn_mma_kernel<<<g2, 128, SM_FLOATS*4>>>(tensor, wo, gamma, out);
}